// round 13
// baseline (speedup 1.0000x reference)
#include <cuda_runtime.h>
#include <math.h>

#define NG     2048
#define IMW    128
#define IMH    128
#define NPIX   (IMW*IMH)
#define EPSV   1e-4f
#define NEARV  0.3f
#define LOG2E  1.4426950408889634f
#define CUTP   (-26.0f)     // skip when power(log2) < CUTP (alpha < ~1.5e-8)

// Render: 8 depth groups x 128 rows x 2 half-rows = 2048 blocks.
// Block = 256 threads = 8 warps = 8 segments (chain 32) within its group.
// Warp = 32 lanes = 32 pixel-pairs spanning 64 px -> cull test warp-uniform.
#define RGROUPS 8
#define RSEGS_B 8
#define CHAIN   (NG/(RGROUPS*RSEGS_B))   // 32
#define NRH     (IMH*2)                  // half-rows
#define HALFW   (31.5f/128.0f)

// Scratch (device globals — no allocation allowed)
__device__ float4 d_sA[NG + 1];   // sorted: u, v, rmax2, Bc (+1 pad for prefetch)
__device__ float4 d_sB[NG];       // Ac, Cc, lopa, cr
__device__ float2 d_sC[NG];       // cg, cb
__device__ float4 d_part[NRH][RGROUPS][64];  // per-(half-row, group) partials
__device__ int    d_cnt[NRH];     // zero-init; reset by last block each run

__device__ __forceinline__ float sigmoidf(float x) { return 1.0f / (1.0f + __expf(-x)); }
__device__ __forceinline__ float ex2f(float x) {
    float y; asm("ex2.approx.ftz.f32 %0, %1;" : "=f"(y) : "f"(x)); return y;
}

// Fused preprocess + stable counting-rank + scatter-to-sorted. 16 blocks x 1024.
// Phase 1: every block (re)computes all 2048 depth keys (cheap: 9 FMA each).
// Phase 2: rank via chunked counting (c = tid>>7 chunk, gl = tid&127 gaussian).
// Phase 3: the 128 owner threads run the full preprocess and write directly
//          into the sorted SoA at their rank.
__global__ void __launch_bounds__(1024) prep_rank_kernel(
    const float* __restrict__ pos, const float* __restrict__ rgb,
    const float* __restrict__ opa, const float* __restrict__ quat,
    const float* __restrict__ scale, const float* __restrict__ rot,
    const float* __restrict__ tran)
{
    __shared__ float sk[NG];
    __shared__ int scnt[128][9];          // 9-pad: conflict-free
    int tid = threadIdx.x;

    float R00 = rot[0], R01 = rot[1], R02 = rot[2];
    float R10 = rot[3], R11 = rot[4], R12 = rot[5];
    float R20 = rot[6], R21 = rot[7], R22 = rot[8];
    float tx = tran[0], ty = tran[1], tz = tran[2];

    #pragma unroll
    for (int i = tid; i < NG; i += 1024) {
        float px = pos[3*i+0], py = pos[3*i+1], pz = pos[3*i+2];
        float x = R00*px + R01*py + R02*pz + tx;
        float y = R10*px + R11*py + R12*pz + ty;
        float z = R20*px + R21*py + R22*pz + tz;
        sk[i] = sqrtf(x*x + y*y + z*z);
    }
    __syncthreads();

    int c  = tid >> 7;                    // 0..7
    int gl = tid & 127;                   // 0..127
    int gi = blockIdx.x * 128 + gl;
    float myk = sk[gi];

    int cnt = 0;
    int j0 = c * (NG/8);
    #pragma unroll 8
    for (int j = j0; j < j0 + NG/8; j++) {
        float kj = sk[j];
        cnt += (kj < myk) || (kj == myk && j < gi);
    }
    scnt[gl][c] = cnt;
    __syncthreads();

    if (c == 0) {
        int rank = 0;
        #pragma unroll
        for (int q = 0; q < 8; q++) rank += scnt[gl][q];

        int i = gi;
        float px = pos[3*i+0], py = pos[3*i+1], pz = pos[3*i+2];
        float x = R00*px + R01*py + R02*pz + tx;
        float y = R10*px + R11*py + R12*pz + ty;
        float z = R20*px + R21*py + R22*pz + tz;

        float invz = 1.0f / z;
        float u = x * invz, v = y * invz;

        float jw00 = (R00 - u*R20)*invz, jw01 = (R01 - u*R21)*invz, jw02 = (R02 - u*R22)*invz;
        float jw10 = (R10 - v*R20)*invz, jw11 = (R11 - v*R21)*invz, jw12 = (R12 - v*R22)*invz;

        float qw = quat[4*i+0], qx = quat[4*i+1], qy = quat[4*i+2], qz = quat[4*i+3];
        float qn = rsqrtf(qw*qw + qx*qx + qy*qy + qz*qz);
        qw *= qn; qx *= qn; qy *= qn; qz *= qn;
        float M00 = 1.0f - 2.0f*(qy*qy + qz*qz), M01 = 2.0f*(qx*qy - qw*qz), M02 = 2.0f*(qx*qz + qw*qy);
        float M10 = 2.0f*(qx*qy + qw*qz), M11 = 1.0f - 2.0f*(qx*qx + qz*qz), M12 = 2.0f*(qy*qz - qw*qx);
        float M20 = 2.0f*(qx*qz - qw*qy), M21 = 2.0f*(qy*qz + qw*qx), M22 = 1.0f - 2.0f*(qx*qx + qy*qy);

        float s0 = fabsf(scale[3*i+0]) + 1e-4f;
        float s1 = fabsf(scale[3*i+1]) + 1e-4f;
        float s2 = fabsf(scale[3*i+2]) + 1e-4f;

        float w00 = (jw00*M00 + jw01*M10 + jw02*M20) * s0;
        float w01 = (jw00*M01 + jw01*M11 + jw02*M21) * s1;
        float w02 = (jw00*M02 + jw01*M12 + jw02*M22) * s2;
        float w10 = (jw10*M00 + jw11*M10 + jw12*M20) * s0;
        float w11 = (jw10*M01 + jw11*M11 + jw12*M21) * s1;
        float w12 = (jw10*M02 + jw11*M12 + jw12*M22) * s2;

        float a = w00*w00 + w01*w01 + w02*w02 + EPSV;
        float b = w00*w10 + w01*w11 + w02*w12;
        float cc = w10*w10 + w11*w11 + w12*w12 + EPSV;

        float invdet = 1.0f / (a*cc - b*b);
        float ia =  cc * invdet;
        float ib = -b * invdet;
        float ic =  a * invdet;

        // power(log2) = Ac*dx^2 + Bc*dx*dy + Cc*dy^2 + lopa
        float Ac = -0.5f * LOG2E * ia;
        float Bc = -LOG2E * ib;
        float Cc = -0.5f * LOG2E * ic;
        float opa_eff = sigmoidf(opa[i]) * ((z > NEARV) ? 1.0f : 0.0f);
        float lopa = log2f(opa_eff);           // -inf when near-culled

        // Least-negative eigenvalue -> conservative skip radius.
        float mh  = 0.5f * (Ac + Cc);
        float dh  = 0.5f * (Ac - Cc);
        float lam = mh + sqrtf(dh*dh + 0.25f*Bc*Bc);   // < 0
        float rmax2 = (CUTP - lopa) / lam;             // -inf when culled

        float cr = sigmoidf(rgb[3*i+0]);
        float cg = sigmoidf(rgb[3*i+1]);
        float cb = sigmoidf(rgb[3*i+2]);

        d_sA[rank] = make_float4(u, v, rmax2, Bc);
        d_sB[rank] = make_float4(Ac, Cc, lopa, cr);
        d_sC[rank] = make_float2(cg, cb);
    }
}

__global__ void __launch_bounds__(RSEGS_B*32) render_kernel(float* __restrict__ out) {
    int tid  = threadIdx.x;
    int lane = tid & 31;               // pixel-pair in 64-px span
    int seg  = tid >> 5;               // 0..7 segment within group
    int idx  = blockIdx.x;
    int grp  = idx & (RGROUPS-1);
    int rh   = idx >> 3;               // half-row id 0..255
    int half = rh & 1;
    int row  = rh >> 1;
    int col0 = half*64 + lane*2;

    float pyf = ((float)row  - 63.5f) * (1.0f/128.0f);
    float px0 = ((float)col0 - 63.5f) * (1.0f/128.0f);
    float px1 = px0 + (1.0f/128.0f);
    float xc  = ((float)(half*64) - 32.0f) * (1.0f/128.0f);

    float T0 = 1.0f, T1 = 1.0f;
    float r0 = 0.f, g0 = 0.f, b0 = 0.f;
    float r1 = 0.f, g1 = 0.f, b1 = 0.f;

    int beg = grp * (NG/RGROUPS) + seg * CHAIN;
    float4 A = d_sA[beg];
    for (int k = beg; k < beg + CHAIN; k++) {
        float4 An = d_sA[k + 1];       // prefetch (pad slot at NG)
        float dy  = pyf - A.y;
        float du  = fabsf(xc - A.x);
        float dxm = fmaxf(du - HALFW, 0.0f);
        if (__fmaf_rn(dy, dy, dxm*dxm) <= A.z) {     // warp-uniform
            float4 B = d_sB[k];
            float2 C = d_sC[k];
            float bdy = A.w * dy;
            float cdy = __fmaf_rn(B.y, dy*dy, B.z);
            float dx0 = px0 - A.x;
            float dx1 = px1 - A.x;
            float a0  = __fmaf_rn(dx0, __fmaf_rn(B.x, dx0, bdy), cdy);
            float a1  = __fmaf_rn(dx1, __fmaf_rn(B.x, dx1, bdy), cdy);
            float al0 = fminf(ex2f(a0), 0.99f);
            float al1 = fminf(ex2f(a1), 0.99f);
            float w0 = T0 * al0, w1 = T1 * al1;
            r0 = __fmaf_rn(w0, B.w, r0);  r1 = __fmaf_rn(w1, B.w, r1);
            g0 = __fmaf_rn(w0, C.x, g0);  g1 = __fmaf_rn(w1, C.x, g1);
            b0 = __fmaf_rn(w0, C.y, b0);  b1 = __fmaf_rn(w1, C.y, b1);
            T0 = __fmaf_rn(-al0, T0, T0);
            T1 = __fmaf_rn(-al1, T1, T1);
        }
        A = An;
    }

    // Combine this block's 8 segments -> group partial for 64 pixels.
    __shared__ float4 part[RSEGS_B][64];
    part[seg][lane*2 + 0] = make_float4(r0, g0, b0, T0);
    part[seg][lane*2 + 1] = make_float4(r1, g1, b1, T1);
    __syncthreads();

    if (tid < 64) {
        float4 p0 = part[0][tid];
        float r = p0.x, g = p0.y, b = p0.z, T = p0.w;
        #pragma unroll
        for (int s = 1; s < RSEGS_B; s++) {
            float4 p = part[s][tid];
            r = __fmaf_rn(T, p.x, r);
            g = __fmaf_rn(T, p.y, g);
            b = __fmaf_rn(T, p.z, b);
            T *= p.w;
        }
        d_part[rh][grp][tid] = make_float4(r, g, b, T);
    }
    __syncthreads();

    // Last-block-done: the 8th block for this half-row combines the groups.
    __shared__ int s_last;
    if (tid == 0) {
        __threadfence();
        s_last = (atomicAdd(&d_cnt[rh], 1) == RGROUPS - 1) ? 1 : 0;
    }
    __syncthreads();
    if (s_last) {
        if (tid < 64) {
            __threadfence();           // acquire: see other blocks' partials
            float4 p[RGROUPS];
            #pragma unroll
            for (int g2 = 0; g2 < RGROUPS; g2++) p[g2] = d_part[rh][g2][tid];
            float r = p[0].x, g = p[0].y, b = p[0].z, T = p[0].w;
            #pragma unroll
            for (int s = 1; s < RGROUPS; s++) {
                r = __fmaf_rn(T, p[s].x, r);
                g = __fmaf_rn(T, p[s].y, g);
                b = __fmaf_rn(T, p[s].z, b);
                T *= p[s].w;
            }
            int pix = row * IMW + half*64 + tid;
            out[pix*3 + 0] = r;
            out[pix*3 + 1] = g;
            out[pix*3 + 2] = b;
        }
        if (tid == 0) d_cnt[rh] = 0;   // reset for next graph replay
    }
}

extern "C" void kernel_launch(void* const* d_in, const int* in_sizes, int n_in,
                              void* d_out, int out_size) {
    const float* pos   = (const float*)d_in[0];
    const float* rgb   = (const float*)d_in[1];
    const float* opa   = (const float*)d_in[2];
    const float* quat  = (const float*)d_in[3];
    const float* scale = (const float*)d_in[4];
    const float* rot   = (const float*)d_in[5];
    const float* tran  = (const float*)d_in[6];
    float* out = (float*)d_out;

    prep_rank_kernel<<<NG/128, 1024>>>(pos, rgb, opa, quat, scale, rot, tran);
    render_kernel<<<NRH*RGROUPS, RSEGS_B*32>>>(out);
}